// round 16
// baseline (speedup 1.0000x reference)
#include <cuda_runtime.h>
#include <cuda_bf16.h>
#include <mma.h>
#include <cstdint>

using namespace nvcuda;

// Problem constants: x (16,800,256), mu (64,256), prec (64) -> out (16, 64*256)
#define BB 16
#define TT 800
#define DD 256
#define KK 64
#define PB  72    // bf16 pitch for phase-A split tiles (rows 144B, 32B-aligned)
#define PGA 72    // f32 pitch for sG (ldm mult of 4)
#define PGC 68    // f32 pitch for phase-C accum scratch

typedef unsigned long long ull;

// ---------------- scratch (device globals; self-cleaning across replays) --------
__device__ float g_acc[BB * KK * DD];   // pool accumulator (RED target)
__device__ float g_S[BB * KK];          // softmax-sum accumulator (RED target)

// ---------------- RED helpers ----------------------------------------------------
__device__ __forceinline__ void red_add_v4(float* p, float x, float y, float z, float w) {
    asm volatile("red.global.add.v4.f32 [%0], {%1,%2,%3,%4};"
                 :: "l"(p), "f"(x), "f"(y), "f"(z), "f"(w) : "memory");
}
__device__ __forceinline__ void red_add_f32(float* p, float v) {
    asm volatile("red.global.add.f32 [%0], %1;" :: "l"(p), "f"(v) : "memory");
}

// ---------------- bf16 split helpers ----------------------------------------------
__device__ __forceinline__ float bftr(float v) {
    return __uint_as_float(__float_as_uint(v) & 0xFFFF0000u);
}
__device__ __forceinline__ uint32_t pbf(float a, float b) {   // {lo=bf(a), hi=bf(b)}
    uint32_t r;
    asm("prmt.b32 %0, %1, %2, 0x7632;" : "=r"(r)
        : "r"(__float_as_uint(a)), "r"(__float_as_uint(b)));
    return r;
}
// 3-split of a float4 into packed-bf16 ulls (h, m, l) — phase A
__device__ __forceinline__ void split3(float4 v, ull& uh, ull& um, ull& ul) {
    float h0 = bftr(v.x), r0 = v.x - h0, m0 = bftr(r0), l0 = bftr(r0 - m0);
    float h1 = bftr(v.y), r1 = v.y - h1, m1 = bftr(r1), l1 = bftr(r1 - m1);
    float h2 = bftr(v.z), r2 = v.z - h2, m2 = bftr(r2), l2 = bftr(r2 - m2);
    float h3 = bftr(v.w), r3 = v.w - h3, m3 = bftr(r3), l3 = bftr(r3 - m3);
    uh = (ull)pbf(h0, h1) | ((ull)pbf(h2, h3) << 32);
    um = (ull)pbf(m0, m1) | ((ull)pbf(m2, m3) << 32);
    ul = (ull)pbf(l0, l1) | ((ull)pbf(l2, l3) << 32);
}
// 2-split — phase C
__device__ __forceinline__ void split2(float4 v, ull& uh, ull& um) {
    float m0 = v.x - bftr(v.x), m1 = v.y - bftr(v.y);
    float m2 = v.z - bftr(v.z), m3 = v.w - bftr(v.w);
    uh = (ull)pbf(v.x, v.y) | ((ull)pbf(v.z, v.w) << 32);
    um = (ull)pbf(m0, m1) | ((ull)pbf(m2, m3) << 32);
}

// split-product pairs for phase A (all of {0,1,2}^2 except (2,2))
__device__ __constant__ const int PAIR_A[8] = {0, 0, 1, 0, 2, 1, 1, 2};
__device__ __constant__ const int PAIR_B[8] = {0, 1, 0, 2, 0, 1, 2, 1};

// smem byte offsets
#define OFF_RH   73728      // r high split: NR x 64 bf16 (pitch 64)
#define OFF_RM   86016      // r mid split
#define OFF_XSQ  99840
#define OFF_MUSQ 100224
#define FUSED_SMEM 100864
// phase C overlays (first 42KB, dead after phase A):
#define OFF_XH   0          // x chunk high split: NR x 64 bf16
#define OFF_XM   12288      // x chunk mid split
#define OFF_GC   24576      // accum scratch: 64 x PGC f32 (17408 B)

// ---------------- fused body: WMMA llk GEMM + softmax + WMMA pool GEMM ----------
template<int NR>
__device__ __forceinline__ void fused_body(int b, int trow0,
                                           const float* __restrict__ x,
                                           const float* __restrict__ mu,
                                           const float* __restrict__ prec) {
    constexpr int RT  = NR / 16;   // staging float4s per thread per chunk
    constexpr int RPW = NR / 8;    // rows per warp (phase B)
    constexpr int TPW = NR / 32;   // phase A mtiles per warp
    constexpr int KS  = NR / 16;   // phase C k-steps (t dim)
    constexpr int XSPB = NR * PB * 2;   // bytes per X split plane (phase A)
    constexpr int MSPB = 64 * PB * 2;   // bytes per MU split plane

    extern __shared__ char sm[];
    char* xsp[3] = { sm, sm + XSPB, sm + 2 * XSPB };
    char* msp[3] = { sm + 3 * XSPB, sm + 3 * XSPB + MSPB, sm + 3 * XSPB + 2 * MSPB };
    float* sG    = (float*)sm;                 // phase-A result overlay
    float* sxsq  = (float*)(sm + OFF_XSQ);
    float* smusq = (float*)(sm + OFF_MUSQ);
    unsigned short* rhw = (unsigned short*)(sm + OFF_RH);
    unsigned short* rmw = (unsigned short*)(sm + OFF_RM);

    int tid  = threadIdx.x;
    int lane = tid & 31;
    int w    = tid >> 5;
    int wr   = w >> 2;     // phase A: 0..1
    int wc   = w & 3;      // phase A ntile

    const float4* x4  = (const float4*)x;
    const float4* mu4 = (const float4*)mu;

    float myxsq[RT];
    #pragma unroll
    for (int i = 0; i < RT; i++) myxsq[i] = 0.f;
    float mymusq[4] = {0.f, 0.f, 0.f, 0.f};

    // prefetch chunk 0 (16 threads per row, j = tid&15)
    float4 px[RT], pm[4];
    #pragma unroll
    for (int ii = 0; ii < RT; ii++) {
        int idx = tid + 256 * ii;
        px[ii] = x4[(trow0 + (idx >> 4)) * 64 + (idx & 15)];
    }
    #pragma unroll
    for (int ii = 0; ii < 4; ii++) {
        int idx = tid + 256 * ii;
        pm[ii] = mu4[(idx >> 4) * 64 + (idx & 15)];
    }

    wmma::fragment<wmma::accumulator, 16, 16, 16, float> fc[TPW];
    #pragma unroll
    for (int t = 0; t < TPW; t++) wmma::fill_fragment(fc[t], 0.f);

    // ---- Phase A: 4 chunks of 64 d; 3-split stage, WMMA accumulate ----
    for (int c = 0; c < 4; c++) {
        #pragma unroll
        for (int ii = 0; ii < RT; ii++) {
            int idx = tid + 256 * ii;
            int row = idx >> 4, j = idx & 15;
            float4 v = px[ii];
            myxsq[ii] += v.x * v.x + v.y * v.y + v.z * v.z + v.w * v.w;
            ull uh, um, ul;
            split3(v, uh, um, ul);
            uint32_t off = (uint32_t)(row * (PB * 2) + j * 8);
            *(ull*)(xsp[0] + off) = uh;
            *(ull*)(xsp[1] + off) = um;
            *(ull*)(xsp[2] + off) = ul;
        }
        #pragma unroll
        for (int ii = 0; ii < 4; ii++) {
            int idx = tid + 256 * ii;
            int row = idx >> 4, j = idx & 15;
            float4 v = pm[ii];
            mymusq[ii] += v.x * v.x + v.y * v.y + v.z * v.z + v.w * v.w;
            ull uh, um, ul;
            split3(v, uh, um, ul);
            uint32_t off = (uint32_t)(row * (PB * 2) + j * 8);
            *(ull*)(msp[0] + off) = uh;
            *(ull*)(msp[1] + off) = um;
            *(ull*)(msp[2] + off) = ul;
        }
        if (c < 3) {   // prefetch next chunk (lands during mma)
            #pragma unroll
            for (int ii = 0; ii < RT; ii++) {
                int idx = tid + 256 * ii;
                px[ii] = x4[(trow0 + (idx >> 4)) * 64 + (c + 1) * 16 + (idx & 15)];
            }
            #pragma unroll
            for (int ii = 0; ii < 4; ii++) {
                int idx = tid + 256 * ii;
                pm[ii] = mu4[(idx >> 4) * 64 + (c + 1) * 16 + (idx & 15)];
            }
        }
        __syncthreads();

        #pragma unroll
        for (int ks = 0; ks < 4; ks++) {
            wmma::fragment<wmma::matrix_b, 16, 16, 16, __nv_bfloat16,
                           wmma::col_major> fb[3];
            #pragma unroll
            for (int s = 0; s < 3; s++)
                wmma::load_matrix_sync(fb[s],
                    (const __nv_bfloat16*)(msp[s]) + wc * 16 * PB + ks * 16, PB);
            wmma::fragment<wmma::matrix_a, 16, 16, 16, __nv_bfloat16,
                           wmma::row_major> fa[TPW][3];
            #pragma unroll
            for (int t = 0; t < TPW; t++) {
                int mt = wr * TPW + t;
                #pragma unroll
                for (int s = 0; s < 3; s++)
                    wmma::load_matrix_sync(fa[t][s],
                        (const __nv_bfloat16*)(xsp[s]) + mt * 16 * PB + ks * 16, PB);
            }
            #pragma unroll
            for (int p = 0; p < 8; p++) {
                int sa = PAIR_A[p], sb = PAIR_B[p];
                #pragma unroll
                for (int t = 0; t < TPW; t++)
                    wmma::mma_sync(fc[t], fa[t][sa], fb[sb], fc[t]);
            }
        }
        __syncthreads();
    }

    // xsq / musq reduce across the 16 staging threads per row
    #pragma unroll
    for (int o = 1; o < 16; o <<= 1) {
        #pragma unroll
        for (int ii = 0; ii < RT; ii++)
            myxsq[ii] += __shfl_xor_sync(0xffffffffu, myxsq[ii], o);
        #pragma unroll
        for (int ii = 0; ii < 4; ii++)
            mymusq[ii] += __shfl_xor_sync(0xffffffffu, mymusq[ii], o);
    }
    if ((tid & 15) == 0) {
        #pragma unroll
        for (int ii = 0; ii < RT; ii++) sxsq[(tid >> 4) + 16 * ii] = myxsq[ii];
        #pragma unroll
        for (int ii = 0; ii < 4; ii++)  smusq[(tid >> 4) + 16 * ii] = mymusq[ii];
    }

    // dump G tiles to sG (overlay on split region)
    #pragma unroll
    for (int t = 0; t < TPW; t++) {
        int mt = wr * TPW + t;
        wmma::store_matrix_sync(sG + mt * 16 * PGA + wc * 16, fc[t], PGA,
                                wmma::mem_row_major);
    }
    __syncthreads();

    // ---- Phase B: softmax over K; write r as bf16 split planes ----
    {
        float p0 = prec[lane], p1 = prec[lane + 32];
        float pp0 = p0 * p0, pp1 = p1 * p1;
        float mq0 = smusq[lane], mq1 = smusq[lane + 32];

        float l0[RPW], l1[RPW], mx[RPW], sms[RPW];
        #pragma unroll
        for (int rr = 0; rr < RPW; rr++) {
            int row = w * RPW + rr;
            float xq = sxsq[row];
            float G0 = sG[row * PGA + lane];
            float G1 = sG[row * PGA + lane + 32];
            l0[rr] = -pp0 * (xq - 2.f * G0 + mq0);
            l1[rr] = -pp1 * (xq - 2.f * G1 + mq1);
            mx[rr] = fmaxf(l0[rr], l1[rr]);
        }
        #pragma unroll
        for (int o = 16; o; o >>= 1)
            #pragma unroll
            for (int rr = 0; rr < RPW; rr++)
                mx[rr] = fmaxf(mx[rr], __shfl_xor_sync(0xffffffffu, mx[rr], o));
        #pragma unroll
        for (int rr = 0; rr < RPW; rr++) {
            l0[rr] = __expf(l0[rr] - mx[rr]);
            l1[rr] = __expf(l1[rr] - mx[rr]);
            sms[rr] = l0[rr] + l1[rr];
        }
        #pragma unroll
        for (int o = 16; o; o >>= 1)
            #pragma unroll
            for (int rr = 0; rr < RPW; rr++)
                sms[rr] += __shfl_xor_sync(0xffffffffu, sms[rr], o);

        float ss0 = 0.f, ss1 = 0.f;
        #pragma unroll
        for (int rr = 0; rr < RPW; rr++) {
            int row = w * RPW + rr;
            float inv = 1.f / sms[rr];
            float r0 = l0[rr] * inv, r1 = l1[rr] * inv;
            // truncation split: h = top16(r), m = top16(r - h)
            rhw[row * 64 + lane]      = (unsigned short)(__float_as_uint(r0) >> 16);
            rmw[row * 64 + lane]      =
                (unsigned short)(__float_as_uint(r0 - bftr(r0)) >> 16);
            rhw[row * 64 + lane + 32] = (unsigned short)(__float_as_uint(r1) >> 16);
            rmw[row * 64 + lane + 32] =
                (unsigned short)(__float_as_uint(r1 - bftr(r1)) >> 16);
            ss0 += r0; ss1 += r1;
        }
        red_add_f32(g_S + b * 64 + lane,      ss0);
        red_add_f32(g_S + b * 64 + lane + 32, ss1);
    }
    __syncthreads();   // r splits visible before phase C

    // ---- Phase C: WMMA pool GEMM, 2-split, d-chunked (4 x 64 d) ----
    {
        char* xh = sm + OFF_XH;
        char* xm = sm + OFF_XM;
        float* sGc = (float*)(sm + OFF_GC);
        const __nv_bfloat16* rhp = (const __nv_bfloat16*)(sm + OFF_RH);
        const __nv_bfloat16* rmp = (const __nv_bfloat16*)(sm + OFF_RM);
        int mt = w >> 1;          // k tile 0..3
        int n0 = (w & 1) * 2;     // 2 d-tiles per warp
        float* ob = g_acc + b * (KK * DD);

        for (int ch = 0; ch < 4; ch++) {
            // stage x chunk splits: NR rows x 64 d, bf16 h/m planes (pitch 64)
            #pragma unroll
            for (int ii = 0; ii < RT; ii++) {
                int idx = tid + 256 * ii;
                int row = idx >> 4, j = idx & 15;
                float4 v = x4[(trow0 + row) * 64 + ch * 16 + j];
                ull uh, um;
                split2(v, uh, um);
                *(ull*)(xh + row * 128 + j * 8) = uh;
                *(ull*)(xm + row * 128 + j * 8) = um;
            }
            __syncthreads();

            wmma::fragment<wmma::accumulator, 16, 16, 16, float> pc0, pc1;
            wmma::fill_fragment(pc0, 0.f);
            wmma::fill_fragment(pc1, 0.f);
            #pragma unroll
            for (int ks = 0; ks < KS; ks++) {
                wmma::fragment<wmma::matrix_a, 16, 16, 16, __nv_bfloat16,
                               wmma::col_major> fah, fam;
                wmma::load_matrix_sync(fah, rhp + ks * 16 * 64 + mt * 16, 64);
                wmma::load_matrix_sync(fam, rmp + ks * 16 * 64 + mt * 16, 64);
                wmma::fragment<wmma::matrix_b, 16, 16, 16, __nv_bfloat16,
                               wmma::row_major> fbh0, fbh1, fbm0, fbm1;
                const __nv_bfloat16* xhp = (const __nv_bfloat16*)xh;
                const __nv_bfloat16* xmp = (const __nv_bfloat16*)xm;
                wmma::load_matrix_sync(fbh0, xhp + ks * 16 * 64 + n0 * 16, 64);
                wmma::load_matrix_sync(fbh1, xhp + ks * 16 * 64 + (n0 + 1) * 16, 64);
                wmma::load_matrix_sync(fbm0, xmp + ks * 16 * 64 + n0 * 16, 64);
                wmma::load_matrix_sync(fbm1, xmp + ks * 16 * 64 + (n0 + 1) * 16, 64);
                wmma::mma_sync(pc0, fah, fbh0, pc0);   // h*h
                wmma::mma_sync(pc1, fah, fbh1, pc1);
                wmma::mma_sync(pc0, fah, fbm0, pc0);   // h*m
                wmma::mma_sync(pc1, fah, fbm1, pc1);
                wmma::mma_sync(pc0, fam, fbh0, pc0);   // m*h
                wmma::mma_sync(pc1, fam, fbh1, pc1);
            }
            wmma::store_matrix_sync(sGc + mt * 16 * PGC + n0 * 16, pc0, PGC,
                                    wmma::mem_row_major);
            wmma::store_matrix_sync(sGc + mt * 16 * PGC + (n0 + 1) * 16, pc1, PGC,
                                    wmma::mem_row_major);
            __syncthreads();

            // RED the 64x64 chunk into g_acc
            #pragma unroll
            for (int hh = 0; hh < 4; hh++) {
                int fi = tid + 256 * hh;       // f4 index in chunk [0, 1024)
                int k  = fi >> 4, d4 = fi & 15;
                float4 v = *(const float4*)(sGc + k * PGC + 4 * d4);
                red_add_v4(ob + k * DD + ch * 64 + d4 * 4, v.x, v.y, v.z, v.w);
            }
            __syncthreads();   // scratch + x planes reusable next chunk
        }
    }
}

__global__ __launch_bounds__(256, 1)
void fused_kernel(const float* __restrict__ x, const float* __restrict__ mu,
                  const float* __restrict__ prec) {
    int bx = blockIdx.x;
    if (bx < 128) {
        int b = bx >> 3;
        fused_body<96>(b, b * TT + (bx & 7) * 96, x, mu, prec);
    } else {
        int b = bx - 128;
        fused_body<32>(b, b * TT + 768, x, mu, prec);
    }
}

// ---------------- finalize: out = (g_acc - mu*S)/(S+1e-9); self-clean -----------
__global__ __launch_bounds__(512, 2)
void finalize_kernel(const float* __restrict__ mu, float* __restrict__ out) {
    int tid = threadIdx.x;
    int bx  = blockIdx.x;
    int b   = bx >> 3;
    int k0  = (bx & 7) * 8;
    int i   = bx * 512 + tid;
    int k   = k0 + (tid >> 6);

    float S = g_S[b * 64 + k];
    float inv = 1.f / (S + 1e-9f);
    float4 a = ((const float4*)g_acc)[i];
    float4 m = ((const float4*)mu)[i & 4095];
    float4 o;
    o.x = (a.x - m.x * S) * inv;
    o.y = (a.y - m.y * S) * inv;
    o.z = (a.z - m.z * S) * inv;
    o.w = (a.w - m.w * S) * inv;
    ((float4*)out)[i] = o;
    ((float4*)g_acc)[i] = make_float4(0.f, 0.f, 0.f, 0.f);

    __syncthreads();
    if (tid < 8) g_S[b * 64 + k0 + tid] = 0.f;
}

// ---------------- launcher --------------------------------------------------------
extern "C" void kernel_launch(void* const* d_in, const int* in_sizes, int n_in,
                              void* d_out, int out_size) {
    const float* x    = (const float*)d_in[0];
    const float* mu   = (const float*)d_in[1];
    const float* prec = (const float*)d_in[2];
    float* out = (float*)d_out;

    cudaFuncSetAttribute(fused_kernel, cudaFuncAttributeMaxDynamicSharedMemorySize,
                         FUSED_SMEM);

    fused_kernel<<<144, 256, FUSED_SMEM>>>(x, mu, prec);
    finalize_kernel<<<128, 512>>>(mu, out);
}

// round 17
// speedup vs baseline: 1.3775x; 1.3775x over previous
#include <cuda_runtime.h>
#include <cuda_bf16.h>
#include <mma.h>
#include <cstdint>

using namespace nvcuda;

// Problem constants: x (16,800,256), mu (64,256), prec (64) -> out (16, 64*256)
#define BB 16
#define TT 800
#define DD 256
#define KK 64
#define PB  72    // bf16 pitch for phase-A split tiles (rows 144B, 32B-aligned)
#define PGA 72    // f32 pitch for sG (ldm mult of 4)

typedef unsigned long long ull;

// ---------------- scratch (device globals; self-cleaning across replays) --------
__device__ float g_acc[BB * KK * DD];   // pool accumulator (RED target)
__device__ float g_S[BB * KK];          // softmax-sum accumulator (RED target)

// ---------------- f32x2 / RED helpers -------------------------------------------
__device__ __forceinline__ ull pack2(float lo, float hi) {
    ull r; asm("mov.b64 %0,{%1,%2};" : "=l"(r) : "f"(lo), "f"(hi)); return r;
}
__device__ __forceinline__ ull fma2(ull a, ull b, ull c) {
    ull d; asm("fma.rn.f32x2 %0,%1,%2,%3;" : "=l"(d) : "l"(a), "l"(b), "l"(c)); return d;
}
__device__ __forceinline__ float2 unpack2(ull v) {
    float2 f; asm("mov.b64 {%0,%1},%2;" : "=f"(f.x), "=f"(f.y) : "l"(v)); return f;
}
__device__ __forceinline__ void red_add_v4(float* p, float x, float y, float z, float w) {
    asm volatile("red.global.add.v4.f32 [%0], {%1,%2,%3,%4};"
                 :: "l"(p), "f"(x), "f"(y), "f"(z), "f"(w) : "memory");
}
__device__ __forceinline__ void red_add_f32(float* p, float v) {
    asm volatile("red.global.add.f32 [%0], %1;" :: "l"(p), "f"(v) : "memory");
}

union F4 { float4 f; ull u[2]; };

// ---------------- bf16 3-split helpers -------------------------------------------
__device__ __forceinline__ float bftr(float v) {
    return __uint_as_float(__float_as_uint(v) & 0xFFFF0000u);
}
__device__ __forceinline__ uint32_t pbf(float a, float b) {   // {lo=bf(a), hi=bf(b)}
    uint32_t r;
    asm("prmt.b32 %0, %1, %2, 0x7632;" : "=r"(r)
        : "r"(__float_as_uint(a)), "r"(__float_as_uint(b)));
    return r;
}
__device__ __forceinline__ void split3(float4 v, ull& uh, ull& um, ull& ul) {
    float h0 = bftr(v.x), r0 = v.x - h0, m0 = bftr(r0), l0 = bftr(r0 - m0);
    float h1 = bftr(v.y), r1 = v.y - h1, m1 = bftr(r1), l1 = bftr(r1 - m1);
    float h2 = bftr(v.z), r2 = v.z - h2, m2 = bftr(r2), l2 = bftr(r2 - m2);
    float h3 = bftr(v.w), r3 = v.w - h3, m3 = bftr(r3), l3 = bftr(r3 - m3);
    uh = (ull)pbf(h0, h1) | ((ull)pbf(h2, h3) << 32);
    um = (ull)pbf(m0, m1) | ((ull)pbf(m2, m3) << 32);
    ul = (ull)pbf(l0, l1) | ((ull)pbf(l2, l3) << 32);
}

// split-product pairs (all of {0,1,2}^2 except (2,2))
__device__ __constant__ const int PAIR_A[8] = {0, 0, 1, 0, 2, 1, 1, 2};
__device__ __constant__ const int PAIR_B[8] = {0, 1, 0, 2, 0, 1, 2, 1};

// smem byte offsets (fixed, valid for both NR variants)
#define OFF_SG   41472      // sG: NR x PGA f32 (over dead mu-split region)
#define OFF_SR   73728      // r: NR x 64 f32
#define OFF_XSQ  99840
#define OFF_MUSQ 100224
#define FUSED_SMEM 100864
// phase C double buffers: [0,16384) and [16384,32768) over dead x-split region

// ---------------- fused body: WMMA llk GEMM + softmax + SIMT pool GEMM ----------
template<int NR>
__device__ __forceinline__ void fused_body(int b, int trow0,
                                           const float* __restrict__ x,
                                           const float* __restrict__ mu,
                                           const float* __restrict__ prec) {
    constexpr int RT  = NR / 16;   // staging float4s per thread per chunk
    constexpr int RPW = NR / 8;    // rows per warp (phase B)
    constexpr int NST = NR / 16;   // phase C stages
    constexpr int TPW = NR / 32;   // phase A mtiles per warp
    constexpr int XSPB = NR * PB * 2;   // bytes per X split plane
    constexpr int MSPB = 64 * PB * 2;   // bytes per MU split plane

    extern __shared__ char sm[];
    char* xsp[3] = { sm, sm + XSPB, sm + 2 * XSPB };
    char* msp[3] = { sm + 3 * XSPB, sm + 3 * XSPB + MSPB, sm + 3 * XSPB + 2 * MSPB };
    float* sG    = (float*)(sm + OFF_SG);      // no longer overlaps phase-C bufs
    float* sr    = (float*)(sm + OFF_SR);
    float* sxsq  = (float*)(sm + OFF_XSQ);
    float* smusq = (float*)(sm + OFF_MUSQ);

    int tid  = threadIdx.x;
    int lane = tid & 31;
    int w    = tid >> 5;
    int wr   = w >> 2;
    int wc   = w & 3;

    const float4* x4  = (const float4*)x;
    const float4* mu4 = (const float4*)mu;

    float myxsq[RT];
    #pragma unroll
    for (int i = 0; i < RT; i++) myxsq[i] = 0.f;
    float mymusq[4] = {0.f, 0.f, 0.f, 0.f};

    // prefetch chunk 0 (16 threads per row, j = tid&15)
    float4 px[RT], pm[4];
    #pragma unroll
    for (int ii = 0; ii < RT; ii++) {
        int idx = tid + 256 * ii;
        px[ii] = x4[(trow0 + (idx >> 4)) * 64 + (idx & 15)];
    }
    #pragma unroll
    for (int ii = 0; ii < 4; ii++) {
        int idx = tid + 256 * ii;
        pm[ii] = mu4[(idx >> 4) * 64 + (idx & 15)];
    }

    float4 pcc[4];   // phase C stage prefetch registers

    wmma::fragment<wmma::accumulator, 16, 16, 16, float> fc[TPW];
    #pragma unroll
    for (int t = 0; t < TPW; t++) wmma::fill_fragment(fc[t], 0.f);

    // ---- Phase A: 4 chunks of 64 d; 3-split stage, WMMA accumulate ----
    for (int c = 0; c < 4; c++) {
        #pragma unroll
        for (int ii = 0; ii < RT; ii++) {
            int idx = tid + 256 * ii;
            int row = idx >> 4, j = idx & 15;
            float4 v = px[ii];
            myxsq[ii] += v.x * v.x + v.y * v.y + v.z * v.z + v.w * v.w;
            ull uh, um, ul;
            split3(v, uh, um, ul);
            uint32_t off = (uint32_t)(row * (PB * 2) + j * 8);
            *(ull*)(xsp[0] + off) = uh;
            *(ull*)(xsp[1] + off) = um;
            *(ull*)(xsp[2] + off) = ul;
        }
        #pragma unroll
        for (int ii = 0; ii < 4; ii++) {
            int idx = tid + 256 * ii;
            int row = idx >> 4, j = idx & 15;
            float4 v = pm[ii];
            mymusq[ii] += v.x * v.x + v.y * v.y + v.z * v.z + v.w * v.w;
            ull uh, um, ul;
            split3(v, uh, um, ul);
            uint32_t off = (uint32_t)(row * (PB * 2) + j * 8);
            *(ull*)(msp[0] + off) = uh;
            *(ull*)(msp[1] + off) = um;
            *(ull*)(msp[2] + off) = ul;
        }
        if (c < 3) {   // prefetch next chunk (lands during mma)
            #pragma unroll
            for (int ii = 0; ii < RT; ii++) {
                int idx = tid + 256 * ii;
                px[ii] = x4[(trow0 + (idx >> 4)) * 64 + (c + 1) * 16 + (idx & 15)];
            }
            #pragma unroll
            for (int ii = 0; ii < 4; ii++) {
                int idx = tid + 256 * ii;
                pm[ii] = mu4[(idx >> 4) * 64 + (c + 1) * 16 + (idx & 15)];
            }
        } else {       // last chunk: prefetch phase-C stage 0 instead
            #pragma unroll
            for (int ii = 0; ii < 4; ii++) {
                int idx = tid + 256 * ii;
                pcc[ii] = x4[(trow0 + (idx >> 6)) * 64 + (idx & 63)];
            }
        }
        __syncthreads();

        #pragma unroll
        for (int ks = 0; ks < 4; ks++) {
            wmma::fragment<wmma::matrix_b, 16, 16, 16, __nv_bfloat16,
                           wmma::col_major> fb[3];
            #pragma unroll
            for (int s = 0; s < 3; s++)
                wmma::load_matrix_sync(fb[s],
                    (const __nv_bfloat16*)(msp[s]) + wc * 16 * PB + ks * 16, PB);
            wmma::fragment<wmma::matrix_a, 16, 16, 16, __nv_bfloat16,
                           wmma::row_major> fa[TPW][3];
            #pragma unroll
            for (int t = 0; t < TPW; t++) {
                int mt = wr * TPW + t;
                #pragma unroll
                for (int s = 0; s < 3; s++)
                    wmma::load_matrix_sync(fa[t][s],
                        (const __nv_bfloat16*)(xsp[s]) + mt * 16 * PB + ks * 16, PB);
            }
            #pragma unroll
            for (int p = 0; p < 8; p++) {
                int sa = PAIR_A[p], sb = PAIR_B[p];
                #pragma unroll
                for (int t = 0; t < TPW; t++)
                    wmma::mma_sync(fc[t], fa[t][sa], fb[sb], fc[t]);
            }
        }
        __syncthreads();   // mma reads done before overwriting split regions
    }

    // stage phase-C buf0 NOW (x-split region dead); lands under phase B
    float4* xsb[2] = { (float4*)sm, (float4*)(sm + 16384) };
    {
        float4* xs0 = xsb[0];
        #pragma unroll
        for (int ii = 0; ii < 4; ii++) xs0[tid + 256 * ii] = pcc[ii];
        if (NST > 1) {   // prefetch stage 1 (lands during phase B)
            #pragma unroll
            for (int ii = 0; ii < 4; ii++) {
                int idx = tid + 256 * ii;
                pcc[ii] = x4[(trow0 + 16 + (idx >> 6)) * 64 + (idx & 63)];
            }
        }
    }

    // xsq / musq reduce across the 16 staging threads per row
    #pragma unroll
    for (int o = 1; o < 16; o <<= 1) {
        #pragma unroll
        for (int ii = 0; ii < RT; ii++)
            myxsq[ii] += __shfl_xor_sync(0xffffffffu, myxsq[ii], o);
        #pragma unroll
        for (int ii = 0; ii < 4; ii++)
            mymusq[ii] += __shfl_xor_sync(0xffffffffu, mymusq[ii], o);
    }
    if ((tid & 15) == 0) {
        #pragma unroll
        for (int ii = 0; ii < RT; ii++) sxsq[(tid >> 4) + 16 * ii] = myxsq[ii];
        #pragma unroll
        for (int ii = 0; ii < 4; ii++)  smusq[(tid >> 4) + 16 * ii] = mymusq[ii];
    }

    // dump G tiles to sG (its region is dead mu-splits; NOT phase-C buffers)
    #pragma unroll
    for (int t = 0; t < TPW; t++) {
        int mt = wr * TPW + t;
        wmma::store_matrix_sync(sG + mt * 16 * PGA + wc * 16, fc[t], PGA,
                                wmma::mem_row_major);
    }
    __syncthreads();

    // ---- Phase B: softmax over K (level-outer shfl loops for ILP) ----
    {
        float p0 = prec[lane], p1 = prec[lane + 32];
        float pp0 = p0 * p0, pp1 = p1 * p1;
        float mq0 = smusq[lane], mq1 = smusq[lane + 32];

        float l0[RPW], l1[RPW], mx[RPW], sms[RPW];
        #pragma unroll
        for (int rr = 0; rr < RPW; rr++) {
            int row = w * RPW + rr;
            float xq = sxsq[row];
            float G0 = sG[row * PGA + lane];
            float G1 = sG[row * PGA + lane + 32];
            l0[rr] = -pp0 * (xq - 2.f * G0 + mq0);
            l1[rr] = -pp1 * (xq - 2.f * G1 + mq1);
            mx[rr] = fmaxf(l0[rr], l1[rr]);
        }
        #pragma unroll
        for (int o = 16; o; o >>= 1)
            #pragma unroll
            for (int rr = 0; rr < RPW; rr++)
                mx[rr] = fmaxf(mx[rr], __shfl_xor_sync(0xffffffffu, mx[rr], o));
        #pragma unroll
        for (int rr = 0; rr < RPW; rr++) {
            l0[rr] = __expf(l0[rr] - mx[rr]);
            l1[rr] = __expf(l1[rr] - mx[rr]);
            sms[rr] = l0[rr] + l1[rr];
        }
        #pragma unroll
        for (int o = 16; o; o >>= 1)
            #pragma unroll
            for (int rr = 0; rr < RPW; rr++)
                sms[rr] += __shfl_xor_sync(0xffffffffu, sms[rr], o);

        float ss0 = 0.f, ss1 = 0.f;
        #pragma unroll
        for (int rr = 0; rr < RPW; rr++) {
            int row = w * RPW + rr;
            float inv = 1.f / sms[rr];
            float r0 = l0[rr] * inv, r1 = l1[rr] * inv;
            sr[row * 64 + lane]      = r0;
            sr[row * 64 + lane + 32] = r1;
            ss0 += r0; ss1 += r1;
        }
        red_add_f32(g_S + b * 64 + lane,      ss0);
        red_add_f32(g_S + b * 64 + lane + 32, ss1);
    }
    __syncthreads();   // sr + buf0 visible before phase C

    // ---- Phase C: pool GEMM (SIMT f32x2), 8k x 8d, buf0 ready, pcc = stage 1 ----
    ull acc2[32];
    #pragma unroll
    for (int i = 0; i < 32; i++) acc2[i] = 0ull;

    for (int st = 0; st < NST; st++) {
        if (st + 1 < NST) {   // store next stage early (hidden under compute)
            float4* xn = xsb[(st + 1) & 1];
            #pragma unroll
            for (int ii = 0; ii < 4; ii++) xn[tid + 256 * ii] = pcc[ii];
        }
        if (st + 2 < NST) {   // prefetch stage st+2
            #pragma unroll
            for (int ii = 0; ii < 4; ii++) {
                int idx = tid + 256 * ii;
                pcc[ii] = x4[(trow0 + (st + 2) * 16 + (idx >> 6)) * 64 + (idx & 63)];
            }
        }
        const float4* xs = xsb[st & 1];
        #pragma unroll
        for (int tt = 0; tt < 16; tt++) {
            const float* rk = sr + (st * 16 + tt) * 64 + w * 8;
            ull rp[4];
            #pragma unroll
            for (int m = 0; m < 4; m++)
                rp[m] = *(const ull*)(rk + 2 * m);    // broadcast LDS.64
            F4 xa, xb;
            xa.f = xs[tt * 64 + lane];
            xb.f = xs[tt * 64 + 32 + lane];
            #pragma unroll
            for (int m = 0; m < 4; m++) {
                float2 rr = unpack2(rp[m]);
                ull r2a = pack2(rr.x, rr.x);
                ull r2b = pack2(rr.y, rr.y);
                int ka = (2 * m) * 4, kb = (2 * m + 1) * 4;
                acc2[ka + 0] = fma2(r2a, xa.u[0], acc2[ka + 0]);
                acc2[ka + 1] = fma2(r2a, xa.u[1], acc2[ka + 1]);
                acc2[ka + 2] = fma2(r2a, xb.u[0], acc2[ka + 2]);
                acc2[ka + 3] = fma2(r2a, xb.u[1], acc2[ka + 3]);
                acc2[kb + 0] = fma2(r2b, xa.u[0], acc2[kb + 0]);
                acc2[kb + 1] = fma2(r2b, xa.u[1], acc2[kb + 1]);
                acc2[kb + 2] = fma2(r2b, xb.u[0], acc2[kb + 2]);
                acc2[kb + 3] = fma2(r2b, xb.u[1], acc2[kb + 3]);
            }
        }
        if (st + 1 < NST) __syncthreads();
    }

    // vector reductions into g_acc (re-zeroed by finalize)
    float* ob = g_acc + b * (KK * DD);
    #pragma unroll
    for (int kk = 0; kk < 8; kk++) {
        int kr = (w * 8 + kk) * DD + 4 * lane;
        float2 a0 = unpack2(acc2[kk * 4 + 0]), a1 = unpack2(acc2[kk * 4 + 1]);
        float2 b0 = unpack2(acc2[kk * 4 + 2]), b1 = unpack2(acc2[kk * 4 + 3]);
        red_add_v4(ob + kr,       a0.x, a0.y, a1.x, a1.y);
        red_add_v4(ob + kr + 128, b0.x, b0.y, b1.x, b1.y);
    }
}

__global__ __launch_bounds__(256, 1)
void fused_kernel(const float* __restrict__ x, const float* __restrict__ mu,
                  const float* __restrict__ prec) {
    int bx = blockIdx.x;
    if (bx < 128) {
        int b = bx >> 3;
        fused_body<96>(b, b * TT + (bx & 7) * 96, x, mu, prec);
    } else {
        int b = bx - 128;
        fused_body<32>(b, b * TT + 768, x, mu, prec);
    }
}

// ---------------- finalize: out = (g_acc - mu*S)/(S+1e-9); self-clean -----------
__global__ __launch_bounds__(512, 2)
void finalize_kernel(const float* __restrict__ mu, float* __restrict__ out) {
    int tid = threadIdx.x;
    int bx  = blockIdx.x;
    int b   = bx >> 3;
    int k0  = (bx & 7) * 8;
    int i   = bx * 512 + tid;
    int k   = k0 + (tid >> 6);

    float S = g_S[b * 64 + k];
    float inv = 1.f / (S + 1e-9f);
    float4 a = ((const float4*)g_acc)[i];
    float4 m = ((const float4*)mu)[i & 4095];
    float4 o;
    o.x = (a.x - m.x * S) * inv;
    o.y = (a.y - m.y * S) * inv;
    o.z = (a.z - m.z * S) * inv;
    o.w = (a.w - m.w * S) * inv;
    ((float4*)out)[i] = o;
    ((float4*)g_acc)[i] = make_float4(0.f, 0.f, 0.f, 0.f);

    __syncthreads();
    if (tid < 8) g_S[b * 64 + k0 + tid] = 0.f;
}

// ---------------- launcher --------------------------------------------------------
extern "C" void kernel_launch(void* const* d_in, const int* in_sizes, int n_in,
                              void* d_out, int out_size) {
    const float* x    = (const float*)d_in[0];
    const float* mu   = (const float*)d_in[1];
    const float* prec = (const float*)d_in[2];
    float* out = (float*)d_out;

    cudaFuncSetAttribute(fused_kernel, cudaFuncAttributeMaxDynamicSharedMemorySize,
                         FUSED_SMEM);

    fused_kernel<<<144, 256, FUSED_SMEM>>>(x, mu, prec);
    finalize_kernel<<<128, 512>>>(mu, out);
}